// round 15
// baseline (speedup 1.0000x reference)
#include <cuda_runtime.h>
#include <cuda_fp16.h>

#define DSZ 192
#define PL  (DSZ * DSZ)
#define NB  2
#define TX  32                   // tile width (x)
#define TY  12                   // tile height (y)
#define ZCH 64                   // z outputs per block (3 chunks cover 192)
#define NT  128
#define HR  16                   // TY + 4  -> 16 rows x 8 chunks = 128 threads exactly
#define PAIRS 35                 // 70 planes processed (68 needed + 2 pad, gated)
#define NBLOCKS (6 * 16 * 6)     // grid size = 576

// A-array: [slot(4 = 2 pairbufs x 2 planes)][row][x] of uint2 {half2(I,J), half2(I2,J2)}
#define IDX(slot,rw,x) (((slot)*HR + (rw))*TX + (x))
#define NELT (4*HR*TX)
// E-array: [pairbuf(2)][row][x] of half2 (IJ_plane0, IJ_plane1)
#define EIDX(pb,rw,x)  (((pb)*HR + (rw))*TX + (x))
#define NELT_E (2*HR*TX)
#define SMEM_BYTES (NELT*8 + NELT_E*4)

// Cross-block reduction state; last block resets it so graph replays are clean.
__device__ float    g_sum    = 0.0f;
__device__ unsigned g_ticket = 0u;

__global__ __launch_bounds__(NT, 4)
void lncc_kernel(const float* __restrict__ pred,
                 const float* __restrict__ targ,
                 float* __restrict__ out)
{
    extern __shared__ char shm[];
    uint2*   const shA  = (uint2*)shm;               // (I,J | I2,J2) packed halves
    __half2* const shEP = (__half2*)(shA + NELT);    // (IJ plane0, IJ plane1)
    __shared__ float blockAcc;

    const int tid = threadIdx.x;
    const int bx = blockIdx.x, by = blockIdx.y;
    const int batch = blockIdx.z / 3;
    const int z0    = (blockIdx.z % 3) * ZCH;

    if (tid == 0) blockAcc = 0.0f;

    // ---- Stage B mapping: ALL 128 threads = 16 rows x 8 x-chunks of 4 ----
    const int  r    = tid >> 3;                 // 0..15
    const int  xq   = tid & 7;
    const int  gy   = by * TY + r - 2;
    const bool rowok = (unsigned)gy < (unsigned)DSZ;
    const int  gx0  = bx * TX + 4 * xq - 2;
    const bool c0 = rowok && ((unsigned)(gx0    ) <= 190u);
    const bool c1 = rowok && ((unsigned)(gx0 + 2) <= 190u);
    const bool c2 = rowok && ((unsigned)(gx0 + 4) <= 190u);
    const bool c3 = rowok && ((unsigned)(gx0 + 6) <= 190u);

    const int gyc = gy < 0 ? 0 : (gy > DSZ - 1 ? DSZ - 1 : gy);
    const long off = (long)batch * DSZ * PL + (long)gyc * DSZ + gx0;
    const float* pB = pred + off;
    const float* tB = targ + off;

    // ---- Stage D mapping: each thread owns 3 adjacent y outputs ----
    const int dy = (tid >> 5) * 3;              // 0,3,6,9
    const int dx = tid & 31;

    // Prefetched, pre-converted state for a plane pair:
    //  P[pl][k]  = half2(p_k, q_k)           (8 regs/plane)
    //  EH[pl][j] = half2(IJsum_{2j}, IJsum_{2j+1})  fp32-computed, rounded (2 regs/plane)
    __half2 P[2][8];
    __half2 EH[2][2];
    const float2 Z2 = make_float2(0.f, 0.f);

    // Load + convert + compute the fp32 IJ x-window sums while floats are live.
#define LOADP(PLN, ZI) do {                                               \
        const int  zi_  = (ZI);                                           \
        const bool zok_ = (unsigned)zi_ < (unsigned)DSZ;                  \
        const long po_  = (long)(zok_ ? zi_ : 0) * PL;                    \
        const float2 La0 = (zok_ && c0) ? *(const float2*)(pB + po_    ) : Z2; \
        const float2 La1 = (zok_ && c1) ? *(const float2*)(pB + po_ + 2) : Z2; \
        const float2 La2 = (zok_ && c2) ? *(const float2*)(pB + po_ + 4) : Z2; \
        const float2 La3 = (zok_ && c3) ? *(const float2*)(pB + po_ + 6) : Z2; \
        const float2 Lb0 = (zok_ && c0) ? *(const float2*)(tB + po_    ) : Z2; \
        const float2 Lb1 = (zok_ && c1) ? *(const float2*)(tB + po_ + 2) : Z2; \
        const float2 Lb2 = (zok_ && c2) ? *(const float2*)(tB + po_ + 4) : Z2; \
        const float2 Lb3 = (zok_ && c3) ? *(const float2*)(tB + po_ + 6) : Z2; \
        const float p0=La0.x,p1=La0.y,p2=La1.x,p3=La1.y;                  \
        const float p4=La2.x,p5=La2.y,p6=La3.x,p7=La3.y;                  \
        const float q0=Lb0.x,q1=Lb0.y,q2=Lb1.x,q3=Lb1.y;                  \
        const float q4=Lb2.x,q5=Lb2.y,q6=Lb3.x,q7=Lb3.y;                  \
        P[PLN][0] = __floats2half2_rn(p0,q0); P[PLN][1] = __floats2half2_rn(p1,q1); \
        P[PLN][2] = __floats2half2_rn(p2,q2); P[PLN][3] = __floats2half2_rn(p3,q3); \
        P[PLN][4] = __floats2half2_rn(p4,q4); P[PLN][5] = __floats2half2_rn(p5,q5); \
        P[PLN][6] = __floats2half2_rn(p6,q6); P[PLN][7] = __floats2half2_rn(p7,q7); \
        const float ij0 = fmaf(p4,q4, fmaf(p3,q3, fmaf(p2,q2, fmaf(p1,q1, p0*q0)))); \
        const float ij1 = fmaf(p5,q5, fmaf(-p0,q0, ij0));                 \
        const float ij2 = fmaf(p6,q6, fmaf(-p1,q1, ij1));                 \
        const float ij3 = fmaf(p7,q7, fmaf(-p2,q2, ij2));                 \
        EH[PLN][0] = __floats2half2_rn(ij0, ij1);                         \
        EH[PLN][1] = __floats2half2_rn(ij2, ij3);                         \
    } while (0)

    // fp16-SIMD x-window sums for I/J and I2/J2 from pre-converted P.
#define BST(PLN, PB) do {                                                          \
        const __half2 P0 = P[PLN][0], P1 = P[PLN][1], P2 = P[PLN][2], P3 = P[PLN][3]; \
        const __half2 P4 = P[PLN][4], P5 = P[PLN][5], P6 = P[PLN][6], P7 = P[PLN][7]; \
        const __half2 A0 = __hadd2(__hadd2(__hadd2(P0,P1), __hadd2(P2,P3)), P4);   \
        const __half2 A1 = __hadd2(A0, __hsub2(P5,P0));                            \
        const __half2 A2 = __hadd2(A1, __hsub2(P6,P1));                            \
        const __half2 A3 = __hadd2(A2, __hsub2(P7,P2));                            \
        const __half2 Q0 = __hfma2(P4,P4, __hfma2(P3,P3, __hfma2(P2,P2,           \
                           __hfma2(P1,P1, __hmul2(P0,P0)))));                      \
        const __half2 N0 = __hneg2(P0), N1h = __hneg2(P1), N2h = __hneg2(P2);      \
        const __half2 Q1 = __hfma2(P5,P5, __hfma2(N0, P0, Q0));                    \
        const __half2 Q2 = __hfma2(P6,P6, __hfma2(N1h,P1, Q1));                    \
        const __half2 Q3 = __hfma2(P7,P7, __hfma2(N2h,P2, Q2));                    \
        const int slot_ = (PB)*2 + (PLN);                                          \
        uint4 u0, u1;                                                              \
        u0.x = *(const unsigned*)&A0;  u0.y = *(const unsigned*)&Q0;               \
        u0.z = *(const unsigned*)&A1;  u0.w = *(const unsigned*)&Q1;               \
        u1.x = *(const unsigned*)&A2;  u1.y = *(const unsigned*)&Q2;               \
        u1.z = *(const unsigned*)&A3;  u1.w = *(const unsigned*)&Q3;               \
        *(uint4*)&shA[IDX(slot_, r, 4*xq)    ] = u0;                               \
        *(uint4*)&shA[IDX(slot_, r, 4*xq) + 2] = u1;                               \
    } while (0)

    // Pair-packed E store: merge per-plane packed IJ sums via lane selects.
#define ESTORE(PB) do {                                                           \
        __half2 t_; uint4 uE;                                                     \
        t_ = __lows2half2 (EH[0][0], EH[1][0]); uE.x = *(unsigned*)&t_;           \
        t_ = __highs2half2(EH[0][0], EH[1][0]); uE.y = *(unsigned*)&t_;           \
        t_ = __lows2half2 (EH[0][1], EH[1][1]); uE.z = *(unsigned*)&t_;           \
        t_ = __highs2half2(EH[0][1], EH[1][1]); uE.w = *(unsigned*)&t_;           \
        *(uint4*)&shEP[EIDX(PB, r, 4*xq)] = uE;                                   \
    } while (0)

    // z rings + incremental running z-window sums (refreshed every 5 pairs)
    __half2 ringA[3][5], ringQ[3][5];
    float   ringE[3][5];
    __half2 SzA[3], SzQ[3];
    float   SzE[3];
    const __half2 HZ = __floats2half2_rn(0.f, 0.f);
#pragma unroll
    for (int o = 0; o < 3; ++o) {
        SzA[o] = HZ; SzQ[o] = HZ; SzE[o] = 0.f;
#pragma unroll
        for (int s = 0; s < 5; ++s) { ringA[o][s] = HZ; ringQ[o][s] = HZ; ringE[o][s] = 0.f; }
    }
    float acc = 0.f;

    // One plane's D work: A/Q loads + SIMD y-sums, incremental z update, NCC.
#define DPLANE(SL, SLOT, IT, YE0, YE1, YE2) do {                                  \
        __half2 a0,a1,a2,a3,a4,a5,a6, q0_,q1_,q2_,q3_,q4_,q5_,q6_;                \
        {                                                                         \
            uint2 w;                                                              \
            w = shA[IDX(SL, dy+0, dx)]; a0=*(__half2*)&w.x; q0_=*(__half2*)&w.y;  \
            w = shA[IDX(SL, dy+1, dx)]; a1=*(__half2*)&w.x; q1_=*(__half2*)&w.y;  \
            w = shA[IDX(SL, dy+2, dx)]; a2=*(__half2*)&w.x; q2_=*(__half2*)&w.y;  \
            w = shA[IDX(SL, dy+3, dx)]; a3=*(__half2*)&w.x; q3_=*(__half2*)&w.y;  \
            w = shA[IDX(SL, dy+4, dx)]; a4=*(__half2*)&w.x; q4_=*(__half2*)&w.y;  \
            w = shA[IDX(SL, dy+5, dx)]; a5=*(__half2*)&w.x; q5_=*(__half2*)&w.y;  \
            w = shA[IDX(SL, dy+6, dx)]; a6=*(__half2*)&w.x; q6_=*(__half2*)&w.y;  \
        }                                                                         \
        __half2 ya_[3], yq_[3];                                                   \
        ya_[0] = __hadd2(__hadd2(__hadd2(a0,a1), __hadd2(a2,a3)), a4);            \
        ya_[1] = __hadd2(ya_[0], __hsub2(a5,a0));                                 \
        ya_[2] = __hadd2(ya_[1], __hsub2(a6,a1));                                 \
        yq_[0] = __hadd2(__hadd2(__hadd2(q0_,q1_), __hadd2(q2_,q3_)), q4_);       \
        yq_[1] = __hadd2(yq_[0], __hsub2(q5_,q0_));                               \
        yq_[2] = __hadd2(yq_[1], __hsub2(q6_,q1_));                               \
        const float ye_[3] = { (YE0), (YE1), (YE2) };                             \
        _Pragma("unroll")                                                         \
        for (int o = 0; o < 3; ++o) {                                             \
            SzA[o] = __hadd2(SzA[o], __hsub2(ya_[o], ringA[o][SLOT]));            \
            ringA[o][SLOT] = ya_[o];                                              \
            SzQ[o] = __hadd2(SzQ[o], __hsub2(yq_[o], ringQ[o][SLOT]));            \
            ringQ[o][SLOT] = yq_[o];                                              \
            SzE[o] += ye_[o] - ringE[o][SLOT];                                    \
            ringE[o][SLOT] = ye_[o];                                              \
        }                                                                         \
        if ((IT) >= 4 && (IT) < ZCH + 4) {                                        \
            _Pragma("unroll")                                                     \
            for (int o = 0; o < 3; ++o) {                                         \
                const float2 sa = __half22float2(SzA[o]);   /* (SI, SJ)   */      \
                const float2 sq = __half22float2(SzQ[o]);   /* (SII, SJJ) */      \
                const float C  = fmaf(125.0f, SzE[o], -sa.x * sa.y);              \
                const float Vi = fmaf(125.0f, sq.x,   -sa.x * sa.x);              \
                const float Vj = fmaf(125.0f, sq.y,   -sa.y * sa.y);              \
                acc += __fdividef(C * C, fmaf(Vi, Vj, 2441.40625f));              \
            }                                                                     \
        }                                                                         \
    } while (0)

    // Joint D for the pair: E loaded once (SIMD y-sums over both planes)
#define DSTPAIR(PB, SLOT0, SLOT1, IT0) do {                                       \
        const __half2 ep0 = shEP[EIDX(PB, dy+0, dx)];                             \
        const __half2 ep1 = shEP[EIDX(PB, dy+1, dx)];                             \
        const __half2 ep2 = shEP[EIDX(PB, dy+2, dx)];                             \
        const __half2 ep3 = shEP[EIDX(PB, dy+3, dx)];                             \
        const __half2 ep4 = shEP[EIDX(PB, dy+4, dx)];                             \
        const __half2 ep5 = shEP[EIDX(PB, dy+5, dx)];                             \
        const __half2 ep6 = shEP[EIDX(PB, dy+6, dx)];                             \
        const __half2 yEP0 = __hadd2(__hadd2(__hadd2(ep0,ep1), __hadd2(ep2,ep3)), ep4); \
        const __half2 yEP1 = __hadd2(yEP0, __hsub2(ep5,ep0));                     \
        const __half2 yEP2 = __hadd2(yEP1, __hsub2(ep6,ep1));                     \
        const float2 f0 = __half22float2(yEP0);                                   \
        const float2 f1 = __half22float2(yEP1);                                   \
        const float2 f2 = __half22float2(yEP2);                                   \
        DPLANE((PB)*2 + 0, SLOT0, (IT0),     f0.x, f1.x, f2.x);                   \
        DPLANE((PB)*2 + 1, SLOT1, (IT0) + 1, f0.y, f1.y, f2.y);                   \
    } while (0)

    // preload pair 0 (planes z0-2, z0-1)
    LOADP(0, z0 - 2); LOADP(1, z0 - 1);

    for (int g = 0; g < PAIRS / 5; ++g) {          // 7 groups of 5 pairs
#pragma unroll
        for (int j = 0; j < 5; ++j) {
            const int pi = g * 5 + j;              // pair index 0..34
            const int pb = (g + j) & 1;
            const int it0 = 2 * pi;                // first plane index of pair

            BST(0, pb);
            BST(1, pb);
            ESTORE(pb);
            if (pi < PAIRS - 1) {                  // prefetch + preconvert next pair
                LOADP(0, z0 + 2 * pi);
                LOADP(1, z0 + 2 * pi + 1);
            }
            __syncthreads();

            DSTPAIR(pb, (2 * j) % 5, (2 * j + 1) % 5, it0);
        }
        // Drift control: rebuild running z-sums exactly from the ring
        // (ring always holds the current 5-plane window, any slot order).
#pragma unroll
        for (int o = 0; o < 3; ++o) {
            SzA[o] = __hadd2(__hadd2(__hadd2(ringA[o][0], ringA[o][1]),
                                     __hadd2(ringA[o][2], ringA[o][3])), ringA[o][4]);
            SzQ[o] = __hadd2(__hadd2(__hadd2(ringQ[o][0], ringQ[o][1]),
                                     __hadd2(ringQ[o][2], ringQ[o][3])), ringQ[o][4]);
            SzE[o] = ((ringE[o][0] + ringE[o][1]) +
                      (ringE[o][2] + ringE[o][3])) + ringE[o][4];
        }
    }

#undef LOADP
#undef BST
#undef ESTORE
#undef DPLANE
#undef DSTPAIR

    // ---- In-block reduction ----
#pragma unroll
    for (int o = 16; o > 0; o >>= 1)
        acc += __shfl_xor_sync(0xffffffffu, acc, o);
    if ((tid & 31) == 0)
        atomicAdd(&blockAcc, acc);
    __syncthreads();

    // ---- Cross-block reduction: last block finalizes and resets state ----
    if (tid == 0) {
        atomicAdd(&g_sum, blockAcc);
        __threadfence();                                   // publish before ticket
        const unsigned t = atomicAdd(&g_ticket, 1u);
        if (t == NBLOCKS - 1) {                            // I'm the last block
            const float s = atomicExch(&g_sum, 0.0f);      // read + reset
            const float INVN = 1.0f / (float)((long)NB * DSZ * DSZ * DSZ);
            out[0] = -s * INVN;
            __threadfence();
            g_ticket = 0u;                                 // restore initial state
        }
    }
}

extern "C" void kernel_launch(void* const* d_in, const int* in_sizes, int n_in,
                              void* d_out, int out_size)
{
    const float* pred = (const float*)d_in[0];
    const float* targ = (const float*)d_in[1];
    float* out = (float*)d_out;

    cudaFuncSetAttribute(lncc_kernel,
                         cudaFuncAttributeMaxDynamicSharedMemorySize, SMEM_BYTES);

    dim3 grid(DSZ / TX, DSZ / TY, NB * 3);   // 6 x 16 x 6 = 576 blocks
    lncc_kernel<<<grid, NT, SMEM_BYTES>>>(pred, targ, out);
}

// round 16
// speedup vs baseline: 1.1205x; 1.1205x over previous
#include <cuda_runtime.h>
#include <cuda_fp16.h>

#define DSZ 192
#define PL  (DSZ * DSZ)
#define NB  2
#define TX  32                   // tile width (x)
#define TY  12                   // tile height (y)
#define ZCH 64                   // z outputs per block (3 chunks cover 192)
#define NT  128
#define HR  16                   // TY + 4  -> 16 rows x 8 chunks = 128 threads exactly
#define PAIRS 35                 // 70 planes processed (68 needed + 2 pad, gated)
#define NBLOCKS (6 * 16 * 6)     // grid size = 576

// A-array: [slot(4 = 2 pairbufs x 2 planes)][row][x] of uint2 {half2(I,J), half2(I2,J2)}
#define IDX(slot,rw,x) (((slot)*HR + (rw))*TX + (x))
#define NELT (4*HR*TX)
// E-array: [pairbuf(2)][row][x] of half2 (IJ_plane0, IJ_plane1)
#define EIDX(pb,rw,x)  (((pb)*HR + (rw))*TX + (x))
#define NELT_E (2*HR*TX)
#define SMEM_BYTES (NELT*8 + NELT_E*4)

// Cross-block reduction state; last block resets it so graph replays are clean.
__device__ float    g_sum    = 0.0f;
__device__ unsigned g_ticket = 0u;

__global__ __launch_bounds__(NT, 4)
void lncc_kernel(const float* __restrict__ pred,
                 const float* __restrict__ targ,
                 float* __restrict__ out)
{
    extern __shared__ char shm[];
    uint2*   const shA  = (uint2*)shm;               // (I,J | I2,J2) packed halves
    __half2* const shEP = (__half2*)(shA + NELT);    // (IJ plane0, IJ plane1)
    __shared__ float blockAcc;

    const int tid = threadIdx.x;
    const int bx = blockIdx.x, by = blockIdx.y;
    const int batch = blockIdx.z / 3;
    const int z0    = (blockIdx.z % 3) * ZCH;

    if (tid == 0) blockAcc = 0.0f;

    // ---- Stage B mapping: ALL 128 threads = 16 rows x 8 x-chunks of 4 ----
    const int  r    = tid >> 3;                 // 0..15
    const int  xq   = tid & 7;
    const int  gy   = by * TY + r - 2;
    const bool rowok = (unsigned)gy < (unsigned)DSZ;
    const int  gx0  = bx * TX + 4 * xq - 2;
    const bool c0 = rowok && ((unsigned)(gx0    ) <= 190u);
    const bool c1 = rowok && ((unsigned)(gx0 + 2) <= 190u);
    const bool c2 = rowok && ((unsigned)(gx0 + 4) <= 190u);
    const bool c3 = rowok && ((unsigned)(gx0 + 6) <= 190u);

    const int gyc = gy < 0 ? 0 : (gy > DSZ - 1 ? DSZ - 1 : gy);
    const long off = (long)batch * DSZ * PL + (long)gyc * DSZ + gx0;
    const float* pB = pred + off;
    const float* tB = targ + off;

    // ---- Stage D mapping: each thread owns 3 adjacent y outputs ----
    const int dy = (tid >> 5) * 3;              // 0,3,6,9
    const int dx = tid & 31;

    float2 Lp[2][4], Lt[2][4];       // prefetched inputs for a plane pair (raw fp32)
    const float2 Z2 = make_float2(0.f, 0.f);

    // Prefetch: raw loads ONLY — no consumers attached (R14 lesson).
#define LOADP(PLN, ZI) do {                                               \
        const int  zi_  = (ZI);                                           \
        const bool zok_ = (unsigned)zi_ < (unsigned)DSZ;                  \
        const long po_  = (long)(zok_ ? zi_ : 0) * PL;                    \
        Lp[PLN][0] = (zok_ && c0) ? *(const float2*)(pB + po_    ) : Z2;  \
        Lp[PLN][1] = (zok_ && c1) ? *(const float2*)(pB + po_ + 2) : Z2;  \
        Lp[PLN][2] = (zok_ && c2) ? *(const float2*)(pB + po_ + 4) : Z2;  \
        Lp[PLN][3] = (zok_ && c3) ? *(const float2*)(pB + po_ + 6) : Z2;  \
        Lt[PLN][0] = (zok_ && c0) ? *(const float2*)(tB + po_    ) : Z2;  \
        Lt[PLN][1] = (zok_ && c1) ? *(const float2*)(tB + po_ + 2) : Z2;  \
        Lt[PLN][2] = (zok_ && c2) ? *(const float2*)(tB + po_ + 4) : Z2;  \
        Lt[PLN][3] = (zok_ && c3) ? *(const float2*)(tB + po_ + 6) : Z2;  \
    } while (0)

    // fp16-SIMD x-window sums: half2(p,q) processes I&J (and II&JJ) together.
    // IJ (cross product) stays fp32 in OIJ.
#define BST(PLN, PB, OIJ) do {                                                     \
        const float p0=Lp[PLN][0].x,p1=Lp[PLN][0].y,p2=Lp[PLN][1].x,p3=Lp[PLN][1].y; \
        const float p4=Lp[PLN][2].x,p5=Lp[PLN][2].y,p6=Lp[PLN][3].x,p7=Lp[PLN][3].y; \
        const float q0=Lt[PLN][0].x,q1=Lt[PLN][0].y,q2=Lt[PLN][1].x,q3=Lt[PLN][1].y; \
        const float q4=Lt[PLN][2].x,q5=Lt[PLN][2].y,q6=Lt[PLN][3].x,q7=Lt[PLN][3].y; \
        const __half2 P0 = __floats2half2_rn(p0,q0), P1 = __floats2half2_rn(p1,q1); \
        const __half2 P2 = __floats2half2_rn(p2,q2), P3 = __floats2half2_rn(p3,q3); \
        const __half2 P4 = __floats2half2_rn(p4,q4), P5 = __floats2half2_rn(p5,q5); \
        const __half2 P6 = __floats2half2_rn(p6,q6), P7 = __floats2half2_rn(p7,q7); \
        const __half2 A0 = __hadd2(__hadd2(__hadd2(P0,P1), __hadd2(P2,P3)), P4);   \
        const __half2 A1 = __hadd2(A0, __hsub2(P5,P0));                            \
        const __half2 A2 = __hadd2(A1, __hsub2(P6,P1));                            \
        const __half2 A3 = __hadd2(A2, __hsub2(P7,P2));                            \
        const __half2 Q0 = __hfma2(P4,P4, __hfma2(P3,P3, __hfma2(P2,P2,           \
                           __hfma2(P1,P1, __hmul2(P0,P0)))));                      \
        const __half2 N0 = __hneg2(P0), N1h = __hneg2(P1), N2h = __hneg2(P2);      \
        const __half2 Q1 = __hfma2(P5,P5, __hfma2(N0, P0, Q0));                    \
        const __half2 Q2 = __hfma2(P6,P6, __hfma2(N1h,P1, Q1));                    \
        const __half2 Q3 = __hfma2(P7,P7, __hfma2(N2h,P2, Q2));                    \
        (OIJ).x = fmaf(p4,q4, fmaf(p3,q3, fmaf(p2,q2, fmaf(p1,q1, p0*q0))));       \
        (OIJ).y = fmaf(p5,q5, fmaf(-p0,q0, (OIJ).x));                              \
        (OIJ).z = fmaf(p6,q6, fmaf(-p1,q1, (OIJ).y));                              \
        (OIJ).w = fmaf(p7,q7, fmaf(-p2,q2, (OIJ).z));                              \
        const int slot_ = (PB)*2 + (PLN);                                          \
        uint4 u0, u1;                                                              \
        u0.x = *(const unsigned*)&A0;  u0.y = *(const unsigned*)&Q0;               \
        u0.z = *(const unsigned*)&A1;  u0.w = *(const unsigned*)&Q1;               \
        u1.x = *(const unsigned*)&A2;  u1.y = *(const unsigned*)&Q2;               \
        u1.z = *(const unsigned*)&A3;  u1.w = *(const unsigned*)&Q3;               \
        *(uint4*)&shA[IDX(slot_, r, 4*xq)    ] = u0;                               \
        *(uint4*)&shA[IDX(slot_, r, 4*xq) + 2] = u1;                               \
    } while (0)

    // Pair-packed E store: half2(IJ_plane0, IJ_plane1) per x-output
#define ESTORE(PB, OIJ0, OIJ1) do {                                               \
        __half2 t_; uint4 uE;                                                     \
        t_ = __floats2half2_rn((OIJ0).x, (OIJ1).x); uE.x = *(unsigned*)&t_;       \
        t_ = __floats2half2_rn((OIJ0).y, (OIJ1).y); uE.y = *(unsigned*)&t_;       \
        t_ = __floats2half2_rn((OIJ0).z, (OIJ1).z); uE.z = *(unsigned*)&t_;       \
        t_ = __floats2half2_rn((OIJ0).w, (OIJ1).w); uE.w = *(unsigned*)&t_;       \
        *(uint4*)&shEP[EIDX(PB, r, 4*xq)] = uE;                                   \
    } while (0)

    // z rings + incremental running z-window sums (refreshed every 5 pairs).
    // E ring: outputs {0,1} packed half2 (slot values are exact fp16 — the y-sums
    // come out of fp16 HADD2 chains), output 2 in fp32.
    __half2 ringA[3][5], ringQ[3][5];
    __half2 ringE01[5];
    float   ringE2[5];
    __half2 SzA[3], SzQ[3];
    __half2 SzE01;
    float   SzE2;
    const __half2 HZ = __floats2half2_rn(0.f, 0.f);
#pragma unroll
    for (int o = 0; o < 3; ++o) {
        SzA[o] = HZ; SzQ[o] = HZ;
#pragma unroll
        for (int s = 0; s < 5; ++s) { ringA[o][s] = HZ; ringQ[o][s] = HZ; }
    }
    SzE01 = HZ; SzE2 = 0.f;
#pragma unroll
    for (int s = 0; s < 5; ++s) { ringE01[s] = HZ; ringE2[s] = 0.f; }
    float acc = 0.f;

    // One plane's D work: A/Q loads + SIMD y-sums, incremental z update, NCC.
    // YE01 = half2(yE_out0, yE_out1) (exact fp16), YE2 = fp32 yE_out2.
#define DPLANE(SL, SLOT, IT, YE01, YE2) do {                                      \
        __half2 a0,a1,a2,a3,a4,a5,a6, q0_,q1_,q2_,q3_,q4_,q5_,q6_;                \
        {                                                                         \
            uint2 w;                                                              \
            w = shA[IDX(SL, dy+0, dx)]; a0=*(__half2*)&w.x; q0_=*(__half2*)&w.y;  \
            w = shA[IDX(SL, dy+1, dx)]; a1=*(__half2*)&w.x; q1_=*(__half2*)&w.y;  \
            w = shA[IDX(SL, dy+2, dx)]; a2=*(__half2*)&w.x; q2_=*(__half2*)&w.y;  \
            w = shA[IDX(SL, dy+3, dx)]; a3=*(__half2*)&w.x; q3_=*(__half2*)&w.y;  \
            w = shA[IDX(SL, dy+4, dx)]; a4=*(__half2*)&w.x; q4_=*(__half2*)&w.y;  \
            w = shA[IDX(SL, dy+5, dx)]; a5=*(__half2*)&w.x; q5_=*(__half2*)&w.y;  \
            w = shA[IDX(SL, dy+6, dx)]; a6=*(__half2*)&w.x; q6_=*(__half2*)&w.y;  \
        }                                                                         \
        __half2 ya_[3], yq_[3];                                                   \
        ya_[0] = __hadd2(__hadd2(__hadd2(a0,a1), __hadd2(a2,a3)), a4);            \
        ya_[1] = __hadd2(ya_[0], __hsub2(a5,a0));                                 \
        ya_[2] = __hadd2(ya_[1], __hsub2(a6,a1));                                 \
        yq_[0] = __hadd2(__hadd2(__hadd2(q0_,q1_), __hadd2(q2_,q3_)), q4_);       \
        yq_[1] = __hadd2(yq_[0], __hsub2(q5_,q0_));                               \
        yq_[2] = __hadd2(yq_[1], __hsub2(q6_,q1_));                               \
        _Pragma("unroll")                                                         \
        for (int o = 0; o < 3; ++o) {                                             \
            SzA[o] = __hadd2(SzA[o], __hsub2(ya_[o], ringA[o][SLOT]));            \
            ringA[o][SLOT] = ya_[o];                                              \
            SzQ[o] = __hadd2(SzQ[o], __hsub2(yq_[o], ringQ[o][SLOT]));            \
            ringQ[o][SLOT] = yq_[o];                                              \
        }                                                                         \
        SzE01 = __hadd2(SzE01, __hsub2((YE01), ringE01[SLOT]));                   \
        ringE01[SLOT] = (YE01);                                                   \
        SzE2 += (YE2) - ringE2[SLOT];                                             \
        ringE2[SLOT] = (YE2);                                                     \
        if ((IT) >= 4 && (IT) < ZCH + 4) {                                        \
            const float2 se01 = __half22float2(SzE01);                            \
            const float SEo[3] = { se01.x, se01.y, SzE2 };                        \
            _Pragma("unroll")                                                     \
            for (int o = 0; o < 3; ++o) {                                         \
                const float2 sa = __half22float2(SzA[o]);   /* (SI, SJ)   */      \
                const float2 sq = __half22float2(SzQ[o]);   /* (SII, SJJ) */      \
                const float C  = fmaf(125.0f, SEo[o], -sa.x * sa.y);              \
                const float Vi = fmaf(125.0f, sq.x,   -sa.x * sa.x);              \
                const float Vj = fmaf(125.0f, sq.y,   -sa.y * sa.y);              \
                acc += __fdividef(C * C, fmaf(Vi, Vj, 2441.40625f));              \
            }                                                                     \
        }                                                                         \
    } while (0)

    // Joint D for the pair: E loaded once (SIMD y-sums over both planes).
    // yEP chains are fp16, so per-plane packing into half2 is lossless.
#define DSTPAIR(PB, SLOT0, SLOT1, IT0) do {                                       \
        const __half2 ep0 = shEP[EIDX(PB, dy+0, dx)];                             \
        const __half2 ep1 = shEP[EIDX(PB, dy+1, dx)];                             \
        const __half2 ep2 = shEP[EIDX(PB, dy+2, dx)];                             \
        const __half2 ep3 = shEP[EIDX(PB, dy+3, dx)];                             \
        const __half2 ep4 = shEP[EIDX(PB, dy+4, dx)];                             \
        const __half2 ep5 = shEP[EIDX(PB, dy+5, dx)];                             \
        const __half2 ep6 = shEP[EIDX(PB, dy+6, dx)];                             \
        const __half2 yEP0 = __hadd2(__hadd2(__hadd2(ep0,ep1), __hadd2(ep2,ep3)), ep4); \
        const __half2 yEP1 = __hadd2(yEP0, __hsub2(ep5,ep0));                     \
        const __half2 yEP2 = __hadd2(yEP1, __hsub2(ep6,ep1));                     \
        /* plane0: lows of yEP*, plane1: highs */                                 \
        const __half2 e01_p0 = __lows2half2 (yEP0, yEP1);                         \
        const __half2 e01_p1 = __highs2half2(yEP0, yEP1);                         \
        const float   e2_p0  = __half2float(__low2half (yEP2));                   \
        const float   e2_p1  = __half2float(__high2half(yEP2));                   \
        DPLANE((PB)*2 + 0, SLOT0, (IT0),     e01_p0, e2_p0);                      \
        DPLANE((PB)*2 + 1, SLOT1, (IT0) + 1, e01_p1, e2_p1);                      \
    } while (0)

    // preload pair 0 (planes z0-2, z0-1)
    LOADP(0, z0 - 2); LOADP(1, z0 - 1);

    for (int g = 0; g < PAIRS / 5; ++g) {          // 7 groups of 5 pairs
#pragma unroll
        for (int j = 0; j < 5; ++j) {
            const int pi = g * 5 + j;              // pair index 0..34
            const int pb = (g + j) & 1;
            const int it0 = 2 * pi;                // first plane index of pair

            float4 oIJ0, oIJ1;
            BST(0, pb, oIJ0);
            BST(1, pb, oIJ1);
            ESTORE(pb, oIJ0, oIJ1);
            if (pi < PAIRS - 1) {                  // prefetch next pair (raw loads only)
                LOADP(0, z0 + 2 * pi);
                LOADP(1, z0 + 2 * pi + 1);
            }
            __syncthreads();

            DSTPAIR(pb, (2 * j) % 5, (2 * j + 1) % 5, it0);
        }
        // Drift control: rebuild running z-sums exactly from the ring.
#pragma unroll
        for (int o = 0; o < 3; ++o) {
            SzA[o] = __hadd2(__hadd2(__hadd2(ringA[o][0], ringA[o][1]),
                                     __hadd2(ringA[o][2], ringA[o][3])), ringA[o][4]);
            SzQ[o] = __hadd2(__hadd2(__hadd2(ringQ[o][0], ringQ[o][1]),
                                     __hadd2(ringQ[o][2], ringQ[o][3])), ringQ[o][4]);
        }
        SzE01 = __hadd2(__hadd2(__hadd2(ringE01[0], ringE01[1]),
                                __hadd2(ringE01[2], ringE01[3])), ringE01[4]);
        SzE2  = ((ringE2[0] + ringE2[1]) + (ringE2[2] + ringE2[3])) + ringE2[4];
    }

#undef LOADP
#undef BST
#undef ESTORE
#undef DPLANE
#undef DSTPAIR

    // ---- In-block reduction ----
#pragma unroll
    for (int o = 16; o > 0; o >>= 1)
        acc += __shfl_xor_sync(0xffffffffu, acc, o);
    if ((tid & 31) == 0)
        atomicAdd(&blockAcc, acc);
    __syncthreads();

    // ---- Cross-block reduction: last block finalizes and resets state ----
    if (tid == 0) {
        atomicAdd(&g_sum, blockAcc);
        __threadfence();                                   // publish before ticket
        const unsigned t = atomicAdd(&g_ticket, 1u);
        if (t == NBLOCKS - 1) {                            // I'm the last block
            const float s = atomicExch(&g_sum, 0.0f);      // read + reset
            const float INVN = 1.0f / (float)((long)NB * DSZ * DSZ * DSZ);
            out[0] = -s * INVN;
            __threadfence();
            g_ticket = 0u;                                 // restore initial state
        }
    }
}

extern "C" void kernel_launch(void* const* d_in, const int* in_sizes, int n_in,
                              void* d_out, int out_size)
{
    const float* pred = (const float*)d_in[0];
    const float* targ = (const float*)d_in[1];
    float* out = (float*)d_out;

    cudaFuncSetAttribute(lncc_kernel,
                         cudaFuncAttributeMaxDynamicSharedMemorySize, SMEM_BYTES);

    dim3 grid(DSZ / TX, DSZ / TY, NB * 3);   // 6 x 16 x 6 = 576 blocks
    lncc_kernel<<<grid, NT, SMEM_BYTES>>>(pred, targ, out);
}

// round 17
// speedup vs baseline: 1.1559x; 1.0316x over previous
#include <cuda_runtime.h>
#include <cuda_fp16.h>

#define DSZ 192
#define PL  (DSZ * DSZ)
#define NB  2
#define TX  32                   // tile width (x)
#define TY  12                   // tile height (y)
#define ZCH 64                   // z outputs per block (3 chunks cover 192)
#define NT  128
#define HR  16                   // TY + 4  -> 16 rows x 8 chunks = 128 threads exactly
#define PAIRS 35                 // 70 planes processed (68 needed + 2 pad, gated)
#define NBLOCKS (6 * 16 * 6)     // grid size = 576

// A-array: [slot(4 = 2 pairbufs x 2 planes)][row][x] of uint2 {half2(I,J), half2(I2,J2)}
#define IDX(slot,rw,x) (((slot)*HR + (rw))*TX + (x))
#define NELT (4*HR*TX)
// E-array: [pairbuf(2)][row][x] of half2 (IJ_plane0, IJ_plane1)
#define EIDX(pb,rw,x)  (((pb)*HR + (rw))*TX + (x))
#define NELT_E (2*HR*TX)
#define SMEM_BYTES (NELT*8 + NELT_E*4)

// Cross-block reduction state; last block resets it so graph replays are clean.
__device__ float    g_sum    = 0.0f;
__device__ unsigned g_ticket = 0u;

__global__ __launch_bounds__(NT, 4)
void lncc_kernel(const float* __restrict__ pred,
                 const float* __restrict__ targ,
                 float* __restrict__ out)
{
    extern __shared__ char shm[];
    uint2*   const shA  = (uint2*)shm;               // (I,J | I2,J2) packed halves
    __half2* const shEP = (__half2*)(shA + NELT);    // (IJ plane0, IJ plane1)
    __shared__ float blockAcc;

    const int tid = threadIdx.x;
    const int bx = blockIdx.x, by = blockIdx.y;
    const int batch = blockIdx.z / 3;
    const int z0    = (blockIdx.z % 3) * ZCH;

    if (tid == 0) blockAcc = 0.0f;

    // ---- Stage B mapping: ALL 128 threads = 16 rows x 8 x-chunks of 4 ----
    const int  r    = tid >> 3;                 // 0..15
    const int  xq   = tid & 7;
    const int  gy   = by * TY + r - 2;
    const bool rowok = (unsigned)gy < (unsigned)DSZ;
    // Aligned base for this chunk's window reads: floats [gxa-2, gxa+6)
    const int  gxa  = bx * TX + 4 * xq;         // 16B-aligned float index, in [0,188]
    const bool cL = rowok && (gxa >= 2);             // left  float2 [gxa-2, gxa)
    const bool cM = rowok;                           // mid   float4 [gxa,   gxa+4)  always in x-range
    const bool cR = rowok && (gxa + 5 <= DSZ - 1);   // right float2 [gxa+4, gxa+6)

    const int gyc = gy < 0 ? 0 : (gy > DSZ - 1 ? DSZ - 1 : gy);
    const long off = (long)batch * DSZ * PL + (long)gyc * DSZ + gxa;
    const float* pB = pred + off;
    const float* tB = targ + off;

    // ---- Stage D mapping: each thread owns 3 adjacent y outputs ----
    const int dy = (tid >> 5) * 3;              // 0,3,6,9
    const int dx = tid & 31;

    // Prefetched inputs for a plane pair: edge float2s + aligned middle float4.
    float2 LpA[2], LpC[2], LtA[2], LtC[2];
    float4 LpM[2], LtM[2];
    const float2 Z2 = make_float2(0.f, 0.f);
    const float4 Z4 = make_float4(0.f, 0.f, 0.f, 0.f);

    // Prefetch: raw loads ONLY — no consumers attached (R14 lesson).
    // Middle LDG.128 is 16B-aligned -> 1 line per warp-row -> 4 wavefronts/instr.
#define LOADP(PLN, ZI) do {                                               \
        const int  zi_  = (ZI);                                           \
        const bool zok_ = (unsigned)zi_ < (unsigned)DSZ;                  \
        const long po_  = (long)(zok_ ? zi_ : 0) * PL;                    \
        LpA[PLN] = (zok_ && cL) ? *(const float2*)(pB + po_ - 2) : Z2;    \
        LpM[PLN] = (zok_ && cM) ? *(const float4*)(pB + po_    ) : Z4;    \
        LpC[PLN] = (zok_ && cR) ? *(const float2*)(pB + po_ + 4) : Z2;    \
        LtA[PLN] = (zok_ && cL) ? *(const float2*)(tB + po_ - 2) : Z2;    \
        LtM[PLN] = (zok_ && cM) ? *(const float4*)(tB + po_    ) : Z4;    \
        LtC[PLN] = (zok_ && cR) ? *(const float2*)(tB + po_ + 4) : Z2;    \
    } while (0)

    // fp16-SIMD x-window sums: half2(p,q) processes I&J (and II&JJ) together.
    // IJ (cross product) stays fp32 in OIJ.
#define BST(PLN, PB, OIJ) do {                                                     \
        const float p0=LpA[PLN].x, p1=LpA[PLN].y;                                  \
        const float p2=LpM[PLN].x, p3=LpM[PLN].y, p4=LpM[PLN].z, p5=LpM[PLN].w;    \
        const float p6=LpC[PLN].x, p7=LpC[PLN].y;                                  \
        const float q0=LtA[PLN].x, q1=LtA[PLN].y;                                  \
        const float q2=LtM[PLN].x, q3=LtM[PLN].y, q4=LtM[PLN].z, q5=LtM[PLN].w;    \
        const float q6=LtC[PLN].x, q7=LtC[PLN].y;                                  \
        const __half2 P0 = __floats2half2_rn(p0,q0), P1 = __floats2half2_rn(p1,q1); \
        const __half2 P2 = __floats2half2_rn(p2,q2), P3 = __floats2half2_rn(p3,q3); \
        const __half2 P4 = __floats2half2_rn(p4,q4), P5 = __floats2half2_rn(p5,q5); \
        const __half2 P6 = __floats2half2_rn(p6,q6), P7 = __floats2half2_rn(p7,q7); \
        const __half2 A0 = __hadd2(__hadd2(__hadd2(P0,P1), __hadd2(P2,P3)), P4);   \
        const __half2 A1 = __hadd2(A0, __hsub2(P5,P0));                            \
        const __half2 A2 = __hadd2(A1, __hsub2(P6,P1));                            \
        const __half2 A3 = __hadd2(A2, __hsub2(P7,P2));                            \
        const __half2 Q0 = __hfma2(P4,P4, __hfma2(P3,P3, __hfma2(P2,P2,           \
                           __hfma2(P1,P1, __hmul2(P0,P0)))));                      \
        const __half2 N0 = __hneg2(P0), N1h = __hneg2(P1), N2h = __hneg2(P2);      \
        const __half2 Q1 = __hfma2(P5,P5, __hfma2(N0, P0, Q0));                    \
        const __half2 Q2 = __hfma2(P6,P6, __hfma2(N1h,P1, Q1));                    \
        const __half2 Q3 = __hfma2(P7,P7, __hfma2(N2h,P2, Q2));                    \
        (OIJ).x = fmaf(p4,q4, fmaf(p3,q3, fmaf(p2,q2, fmaf(p1,q1, p0*q0))));       \
        (OIJ).y = fmaf(p5,q5, fmaf(-p0,q0, (OIJ).x));                              \
        (OIJ).z = fmaf(p6,q6, fmaf(-p1,q1, (OIJ).y));                              \
        (OIJ).w = fmaf(p7,q7, fmaf(-p2,q2, (OIJ).z));                              \
        const int slot_ = (PB)*2 + (PLN);                                          \
        uint4 u0, u1;                                                              \
        u0.x = *(const unsigned*)&A0;  u0.y = *(const unsigned*)&Q0;               \
        u0.z = *(const unsigned*)&A1;  u0.w = *(const unsigned*)&Q1;               \
        u1.x = *(const unsigned*)&A2;  u1.y = *(const unsigned*)&Q2;               \
        u1.z = *(const unsigned*)&A3;  u1.w = *(const unsigned*)&Q3;               \
        *(uint4*)&shA[IDX(slot_, r, 4*xq)    ] = u0;                               \
        *(uint4*)&shA[IDX(slot_, r, 4*xq) + 2] = u1;                               \
    } while (0)

    // Pair-packed E store: half2(IJ_plane0, IJ_plane1) per x-output
#define ESTORE(PB, OIJ0, OIJ1) do {                                               \
        __half2 t_; uint4 uE;                                                     \
        t_ = __floats2half2_rn((OIJ0).x, (OIJ1).x); uE.x = *(unsigned*)&t_;       \
        t_ = __floats2half2_rn((OIJ0).y, (OIJ1).y); uE.y = *(unsigned*)&t_;       \
        t_ = __floats2half2_rn((OIJ0).z, (OIJ1).z); uE.z = *(unsigned*)&t_;       \
        t_ = __floats2half2_rn((OIJ0).w, (OIJ1).w); uE.w = *(unsigned*)&t_;       \
        *(uint4*)&shEP[EIDX(PB, r, 4*xq)] = uE;                                   \
    } while (0)

    // z rings + incremental running z-window sums (refreshed every 5 pairs).
    __half2 ringA[3][5], ringQ[3][5];
    __half2 ringE01[5];
    float   ringE2[5];
    __half2 SzA[3], SzQ[3];
    __half2 SzE01;
    float   SzE2;
    const __half2 HZ = __floats2half2_rn(0.f, 0.f);
#pragma unroll
    for (int o = 0; o < 3; ++o) {
        SzA[o] = HZ; SzQ[o] = HZ;
#pragma unroll
        for (int s = 0; s < 5; ++s) { ringA[o][s] = HZ; ringQ[o][s] = HZ; }
    }
    SzE01 = HZ; SzE2 = 0.f;
#pragma unroll
    for (int s = 0; s < 5; ++s) { ringE01[s] = HZ; ringE2[s] = 0.f; }
    float acc = 0.f;

    // One plane's D work: A/Q loads + SIMD y-sums, incremental z update, NCC.
#define DPLANE(SL, SLOT, IT, YE01, YE2) do {                                      \
        __half2 a0,a1,a2,a3,a4,a5,a6, q0_,q1_,q2_,q3_,q4_,q5_,q6_;                \
        {                                                                         \
            uint2 w;                                                              \
            w = shA[IDX(SL, dy+0, dx)]; a0=*(__half2*)&w.x; q0_=*(__half2*)&w.y;  \
            w = shA[IDX(SL, dy+1, dx)]; a1=*(__half2*)&w.x; q1_=*(__half2*)&w.y;  \
            w = shA[IDX(SL, dy+2, dx)]; a2=*(__half2*)&w.x; q2_=*(__half2*)&w.y;  \
            w = shA[IDX(SL, dy+3, dx)]; a3=*(__half2*)&w.x; q3_=*(__half2*)&w.y;  \
            w = shA[IDX(SL, dy+4, dx)]; a4=*(__half2*)&w.x; q4_=*(__half2*)&w.y;  \
            w = shA[IDX(SL, dy+5, dx)]; a5=*(__half2*)&w.x; q5_=*(__half2*)&w.y;  \
            w = shA[IDX(SL, dy+6, dx)]; a6=*(__half2*)&w.x; q6_=*(__half2*)&w.y;  \
        }                                                                         \
        __half2 ya_[3], yq_[3];                                                   \
        ya_[0] = __hadd2(__hadd2(__hadd2(a0,a1), __hadd2(a2,a3)), a4);            \
        ya_[1] = __hadd2(ya_[0], __hsub2(a5,a0));                                 \
        ya_[2] = __hadd2(ya_[1], __hsub2(a6,a1));                                 \
        yq_[0] = __hadd2(__hadd2(__hadd2(q0_,q1_), __hadd2(q2_,q3_)), q4_);       \
        yq_[1] = __hadd2(yq_[0], __hsub2(q5_,q0_));                               \
        yq_[2] = __hadd2(yq_[1], __hsub2(q6_,q1_));                               \
        _Pragma("unroll")                                                         \
        for (int o = 0; o < 3; ++o) {                                             \
            SzA[o] = __hadd2(SzA[o], __hsub2(ya_[o], ringA[o][SLOT]));            \
            ringA[o][SLOT] = ya_[o];                                              \
            SzQ[o] = __hadd2(SzQ[o], __hsub2(yq_[o], ringQ[o][SLOT]));            \
            ringQ[o][SLOT] = yq_[o];                                              \
        }                                                                         \
        SzE01 = __hadd2(SzE01, __hsub2((YE01), ringE01[SLOT]));                   \
        ringE01[SLOT] = (YE01);                                                   \
        SzE2 += (YE2) - ringE2[SLOT];                                             \
        ringE2[SLOT] = (YE2);                                                     \
        if ((IT) >= 4 && (IT) < ZCH + 4) {                                        \
            const float2 se01 = __half22float2(SzE01);                            \
            const float SEo[3] = { se01.x, se01.y, SzE2 };                        \
            _Pragma("unroll")                                                     \
            for (int o = 0; o < 3; ++o) {                                         \
                const float2 sa = __half22float2(SzA[o]);   /* (SI, SJ)   */      \
                const float2 sq = __half22float2(SzQ[o]);   /* (SII, SJJ) */      \
                const float C  = fmaf(125.0f, SEo[o], -sa.x * sa.y);              \
                const float Vi = fmaf(125.0f, sq.x,   -sa.x * sa.x);              \
                const float Vj = fmaf(125.0f, sq.y,   -sa.y * sa.y);              \
                acc += __fdividef(C * C, fmaf(Vi, Vj, 2441.40625f));              \
            }                                                                     \
        }                                                                         \
    } while (0)

    // Joint D for the pair: E loaded once (SIMD y-sums over both planes).
#define DSTPAIR(PB, SLOT0, SLOT1, IT0) do {                                       \
        const __half2 ep0 = shEP[EIDX(PB, dy+0, dx)];                             \
        const __half2 ep1 = shEP[EIDX(PB, dy+1, dx)];                             \
        const __half2 ep2 = shEP[EIDX(PB, dy+2, dx)];                             \
        const __half2 ep3 = shEP[EIDX(PB, dy+3, dx)];                             \
        const __half2 ep4 = shEP[EIDX(PB, dy+4, dx)];                             \
        const __half2 ep5 = shEP[EIDX(PB, dy+5, dx)];                             \
        const __half2 ep6 = shEP[EIDX(PB, dy+6, dx)];                             \
        const __half2 yEP0 = __hadd2(__hadd2(__hadd2(ep0,ep1), __hadd2(ep2,ep3)), ep4); \
        const __half2 yEP1 = __hadd2(yEP0, __hsub2(ep5,ep0));                     \
        const __half2 yEP2 = __hadd2(yEP1, __hsub2(ep6,ep1));                     \
        const __half2 e01_p0 = __lows2half2 (yEP0, yEP1);                         \
        const __half2 e01_p1 = __highs2half2(yEP0, yEP1);                         \
        const float   e2_p0  = __half2float(__low2half (yEP2));                   \
        const float   e2_p1  = __half2float(__high2half(yEP2));                   \
        DPLANE((PB)*2 + 0, SLOT0, (IT0),     e01_p0, e2_p0);                      \
        DPLANE((PB)*2 + 1, SLOT1, (IT0) + 1, e01_p1, e2_p1);                      \
    } while (0)

    // preload pair 0 (planes z0-2, z0-1)
    LOADP(0, z0 - 2); LOADP(1, z0 - 1);

    for (int g = 0; g < PAIRS / 5; ++g) {          // 7 groups of 5 pairs
#pragma unroll
        for (int j = 0; j < 5; ++j) {
            const int pi = g * 5 + j;              // pair index 0..34
            const int pb = (g + j) & 1;
            const int it0 = 2 * pi;                // first plane index of pair

            float4 oIJ0, oIJ1;
            BST(0, pb, oIJ0);
            BST(1, pb, oIJ1);
            ESTORE(pb, oIJ0, oIJ1);
            if (pi < PAIRS - 1) {                  // prefetch next pair (raw loads only)
                LOADP(0, z0 + 2 * pi);
                LOADP(1, z0 + 2 * pi + 1);
            }
            __syncthreads();

            DSTPAIR(pb, (2 * j) % 5, (2 * j + 1) % 5, it0);
        }
        // Drift control: rebuild running z-sums exactly from the ring.
#pragma unroll
        for (int o = 0; o < 3; ++o) {
            SzA[o] = __hadd2(__hadd2(__hadd2(ringA[o][0], ringA[o][1]),
                                     __hadd2(ringA[o][2], ringA[o][3])), ringA[o][4]);
            SzQ[o] = __hadd2(__hadd2(__hadd2(ringQ[o][0], ringQ[o][1]),
                                     __hadd2(ringQ[o][2], ringQ[o][3])), ringQ[o][4]);
        }
        SzE01 = __hadd2(__hadd2(__hadd2(ringE01[0], ringE01[1]),
                                __hadd2(ringE01[2], ringE01[3])), ringE01[4]);
        SzE2  = ((ringE2[0] + ringE2[1]) + (ringE2[2] + ringE2[3])) + ringE2[4];
    }

#undef LOADP
#undef BST
#undef ESTORE
#undef DPLANE
#undef DSTPAIR

    // ---- In-block reduction ----
#pragma unroll
    for (int o = 16; o > 0; o >>= 1)
        acc += __shfl_xor_sync(0xffffffffu, acc, o);
    if ((tid & 31) == 0)
        atomicAdd(&blockAcc, acc);
    __syncthreads();

    // ---- Cross-block reduction: last block finalizes and resets state ----
    if (tid == 0) {
        atomicAdd(&g_sum, blockAcc);
        __threadfence();                                   // publish before ticket
        const unsigned t = atomicAdd(&g_ticket, 1u);
        if (t == NBLOCKS - 1) {                            // I'm the last block
            const float s = atomicExch(&g_sum, 0.0f);      // read + reset
            const float INVN = 1.0f / (float)((long)NB * DSZ * DSZ * DSZ);
            out[0] = -s * INVN;
            __threadfence();
            g_ticket = 0u;                                 // restore initial state
        }
    }
}

extern "C" void kernel_launch(void* const* d_in, const int* in_sizes, int n_in,
                              void* d_out, int out_size)
{
    const float* pred = (const float*)d_in[0];
    const float* targ = (const float*)d_in[1];
    float* out = (float*)d_out;

    cudaFuncSetAttribute(lncc_kernel,
                         cudaFuncAttributeMaxDynamicSharedMemorySize, SMEM_BYTES);

    dim3 grid(DSZ / TX, DSZ / TY, NB * 3);   // 6 x 16 x 6 = 576 blocks
    lncc_kernel<<<grid, NT, SMEM_BYTES>>>(pred, targ, out);
}